// round 16
// baseline (speedup 1.0000x reference)
#include <cuda_runtime.h>
#include <cuda_bf16.h>
#include <cstdint>

// Gather: out[g][row][j*32+k] = in[row][g*512 + j*64 + k]
//   out flat float4 idx i: g=i>>20, row=(i>>6)&16383, v=i&63
//   src (float4 units) = row*1024 + g*128 + (v>>3)*16 + (v&7)
//
// SINGLE-WAVE PERSISTENT KERNEL. All prior kernels ran 2048-8192 blocks =
// 4-7 waves over the ~1184 resident block slots (148 SMs x 8 blocks at
// 30 regs); each wave transition (~2360 cyc) drains the SMs' outstanding
// load queues -> DRAM idles. This matches the stubborn 27% dram-idle
// fraction seen in every profile. Fix: grid = 148*8 = 1184 blocks, exactly
// one wave, every SM full (2048 thr); each thread grid-strides over ~27
// float4 items with a pairwise front-batched body. No wave transitions ->
// request supply never drains mid-kernel.

#define NBLOCKS 1184u                     // 148 SMs * 8 resident blocks
#define STRIDE  (NBLOCKS * 256u)          // 303104 threads
#define TOTAL   (1u << 23)                // 2^23 float4s

__device__ __forceinline__ unsigned int src_of(unsigned int i)
{
    unsigned int g   = i >> 20;
    unsigned int row = (i >> 6) & 16383u;
    unsigned int v   = i & 63u;
    return row * 1024u + g * 128u + (v >> 3) * 16u + (v & 7u);
}

__global__ void __launch_bounds__(256)
fuse_slice_cat_kernel(const float4* __restrict__ in, float4* __restrict__ out)
{
    unsigned int i = blockIdx.x * 256u + threadIdx.x;

    // Pairwise front-batched persistent loop (~13 pair iterations/thread).
    for (; i + STRIDE < TOTAL; i += 2u * STRIDE) {
        unsigned int i2 = i + STRIDE;
        float4 a = in[src_of(i)];
        float4 b = in[src_of(i2)];
        out[i]  = a;
        out[i2] = b;
    }
    if (i < TOTAL)
        out[i] = in[src_of(i)];
}

extern "C" void kernel_launch(void* const* d_in, const int* in_sizes, int n_in,
                              void* d_out, int out_size)
{
    const float4* in  = (const float4*)d_in[0];
    float4*       out = (float4*)d_out;

    fuse_slice_cat_kernel<<<NBLOCKS, 256>>>(in, out);
}

// round 17
// speedup vs baseline: 1.0926x; 1.0926x over previous
#include <cuda_runtime.h>
#include <cuda_bf16.h>
#include <cstdint>

// Gather: out[g][row][j*32+k] = in[row][g*512 + j*64 + k]
//   out flat float4 idx i: g=i>>20, row=(i>>6)&16383, v=i&63
//   src (float4 units) = row*1024 + g*128 + (v>>3)*16 + (v&7)
//
// TERMINAL KERNEL (R10; best measured 44.128us; runs {44.13, 44.99, 45.12}).
//   * front-batched MLP=4 per thread at regs=30, ~78-84% occupancy,
//   * compile-time-constant grid stride (2^21), linear grid-stride mapping,
//   * multi-wave launch (8192 blocks) — measurably better than single-wave
//     persistent (R16: 49.4us, tail-drain) and every other variant.
// 16-round verdict: structural DRAM roofline. Irreducible 256 MiB/replay
// (128 MiB half-dense reads + 128 MiB dense writes, zero reuse) served at
// ~5.9 TB/s effective. Falsified levers: MLP 8-32 (ptxas re-serializes),
// 256-bit accesses, software pipelining, all L2 eviction-class residency
// schemes (no cross-replay effect), concurrency remaps, block-granularity
// tuning, single-wave persistence (regressed).

#define GRID_BLOCKS 8192u
#define STRIDE      (GRID_BLOCKS * 256u)   // 2^21 float4s

__global__ void __launch_bounds__(256)
fuse_slice_cat_kernel(const float4* __restrict__ in, float4* __restrict__ out)
{
    const unsigned int i0 = blockIdx.x * 256u + threadIdx.x;

    unsigned int idx[4];
    unsigned int srcI[4];

    #pragma unroll
    for (int it = 0; it < 4; ++it) {
        unsigned int i   = i0 + (unsigned)it * STRIDE;
        unsigned int g   = i >> 20;
        unsigned int row = (i >> 6) & 16383u;
        unsigned int v   = i & 63u;
        idx[it]  = i;
        srcI[it] = row * 1024u + g * 128u + (v >> 3) * 16u + (v & 7u);
    }

    float4 r[4];
    #pragma unroll
    for (int it = 0; it < 4; ++it)      // 4 loads in flight before any store
        r[it] = in[srcI[it]];

    #pragma unroll
    for (int it = 0; it < 4; ++it)
        out[idx[it]] = r[it];
}

extern "C" void kernel_launch(void* const* d_in, const int* in_sizes, int n_in,
                              void* d_out, int out_size)
{
    const float4* in  = (const float4*)d_in[0];
    float4*       out = (float4*)d_out;

    fuse_slice_cat_kernel<<<GRID_BLOCKS, 256>>>(in, out);
}